// round 15
// baseline (speedup 1.0000x reference)
#include <cuda_runtime.h>
#include <cuda_bf16.h>
#include <cstdint>

// ---------------------------------------------------------------------------
// g_Bf: W1 bf16 fragments, coalesced uint4 per (ks, t, lane):
//   uint4 index e = (ks*7 + tt)*32 + lane, lane = nr*4 + fq, n = tt*8 + nr
//   bf16[e*8 + half*2+par]   = hi of W1[k = ks*16 + half*8 + fq*2 + par][n]
//   bf16[e*8 + 4+half*2+par] = lo
// Total 7168 uint4 = 114688 B. Each CTA builds uint4s [bid*7, bid*7+7)
// (28 worker threads, one (k,n,half,par) cell each); grid flag gates reads.
// ---------------------------------------------------------------------------
static __device__ __align__(16) __nv_bfloat16 g_Bf[7168 * 8];  // 114688 B
static __device__ __align__(16) float g_W2[112];  // [56][2], rows >= 50 zero
static __device__ __align__(8)  float g_b1[56];   // zero-padded
static __device__ __align__(8)  float g_b2[2];
static __device__ unsigned g_done = 0;  // builder completions (reset at exit)
static __device__ unsigned g_exit = 0;  // CTA exits (reset at exit)

// ---------------- helpers ----------------
__device__ __forceinline__ uint32_t smem_u32(const void* p) {
    uint32_t a;
    asm("{ .reg .u64 t; cvta.to.shared.u64 t, %1; cvt.u32.u64 %0, t; }" : "=r"(a) : "l"(p));
    return a;
}
__device__ __forceinline__ void cp16(uint32_t dst, const void* src) {
    asm volatile("cp.async.cg.shared.global [%0], [%1], 16;" :: "r"(dst), "l"(src) : "memory");
}
__device__ __forceinline__ void cp16z(uint32_t dst, const void* src) {
    asm volatile("cp.async.cg.shared.global [%0], [%1], 16, 0;" :: "r"(dst), "l"(src) : "memory");
}
__device__ __forceinline__ void split2(float vx, float vy, uint32_t& h, uint32_t& l) {
    __nv_bfloat162 hb = __floats2bfloat162_rn(vx, vy);
    float rx = vx - __bfloat162float(hb.x);
    float ry = vy - __bfloat162float(hb.y);
    __nv_bfloat162 lb = __floats2bfloat162_rn(rx, ry);
    h = (uint32_t)__bfloat16_as_ushort(hb.x) | ((uint32_t)__bfloat16_as_ushort(hb.y) << 16);
    l = (uint32_t)__bfloat16_as_ushort(lb.x) | ((uint32_t)__bfloat16_as_ushort(lb.y) << 16);
}
__device__ __forceinline__ void mma16816(float* d, uint32_t a0, uint32_t a1,
                                         uint32_t a2, uint32_t a3,
                                         uint32_t b0, uint32_t b1) {
    asm volatile(
        "mma.sync.aligned.m16n8k16.row.col.f32.bf16.bf16.f32 "
        "{%0,%1,%2,%3}, {%4,%5,%6,%7}, {%8,%9}, {%0,%1,%2,%3};"
        : "+f"(d[0]), "+f"(d[1]), "+f"(d[2]), "+f"(d[3])
        : "r"(a0), "r"(a1), "r"(a2), "r"(a3), "r"(b0), "r"(b1));
}

// ---- smem layout (floats) ----
// x: per-warp 3-stage ring, 32 rows x 20 floats per stage (conflict-free pad).
// B: CTA-shared 3-stage ring, 3584 B per stage.
static constexpr int NW      = 2;                       // warps per CTA
static constexpr int THREADS = NW * 32;                 // 64
static constexpr int ROW_F   = 20;
static constexpr int STAGES  = 3;
static constexpr int STAGE_F = 32 * ROW_F;              // 640 floats
static constexpr int XW_F    = STAGES * STAGE_F;        // 1920 floats / warp
static constexpr int O_B_F   = NW * XW_F;               // 3840
static constexpr int BSTG_F  = 896;                     // 3584 B per B stage
static constexpr int SMEM_TOTAL = (O_B_F + STAGES * BSTG_F) * 4;  // 26112 B

__device__ __forceinline__ void load_x_chunk(uint32_t wstage_b, const float* xw,
                                             int ks, int lane) {
    #pragma unroll
    for (int i = 0; i < 4; ++i) {
        const int c = lane + 32 * i;
        const int rowl = c >> 2, c4 = c & 3;
        const int kb = ks * 16 + c4 * 4;
        const uint32_t dst = wstage_b + (uint32_t)(rowl * ROW_F + c4 * 4) * 4u;
        if (kb + 4 <= 500) cp16(dst, xw + (size_t)rowl * 500 + kb);
        else               cp16z(dst, xw);
    }
}

// ---------------- single fused kernel ----------------
// 1024 CTAs x 64 threads, ~7-8 CTAs/SM (single wave). Warp: 32 rows x 56 cols.
__global__ void __launch_bounds__(THREADS, 8)
tn_forward(const float* __restrict__ x, float* __restrict__ out,
           const float* __restrict__ A1, const float* __restrict__ A2,
           const float* __restrict__ A3, const float* __restrict__ A4,
           const float* __restrict__ A5, const float* __restrict__ b1,
           const float* __restrict__ B1, const float* __restrict__ B2,
           const float* __restrict__ B3, const float* __restrict__ b2) {
    extern __shared__ float sm[];
    const uint32_t sbase = smem_u32(sm);
    const int tid = threadIdx.x;
    const int warp = tid >> 5, lane = tid & 31;
    const int q = lane & 3, nrow = lane >> 2;

    const size_t row0 = (size_t)blockIdx.x * 64;
    const float* xw = x + (row0 + (size_t)warp * 32) * 500;
    const uint32_t xwbase = sbase + (uint32_t)warp * XW_F * 4u;
    const uint32_t bbase = sbase + (uint32_t)O_B_F * 4u;
    const char* gB = reinterpret_cast<const char*>(g_Bf);

    // issue x prefetch for chunks 0..S-2 (uncommitted; overlaps weight build)
    #pragma unroll
    for (int s = 0; s < STAGES - 1; ++s)
        load_x_chunk(xwbase + s * STAGE_F * 4, xw, s, lane);

    // ---- distributed weight build: this CTA owns uint4s [bid*7, bid*7+7) ----
    if (tid < 28) {
        const int u = tid >> 2, hp = tid & 3;
        const int e = blockIdx.x * 7 + u;
        const int lane_f = e & 31, tt = (e >> 5) % 7, ks = (e >> 5) / 7;
        const int nr = lane_f >> 2, fq = lane_f & 3;
        const int n = tt * 8 + nr;
        const int k = ks * 16 + (hp >> 1) * 8 + fq * 2 + (hp & 1);
        float val = 0.f;
        if (k < 500 && n < 50) {
            const int i = k / 250, j = (k / 50) % 5, kk = (k / 10) % 5;
            const int l = (k >> 1) % 5, m = k & 1;
            const int v = n / 10, w = (n >> 1) % 5, xo = n & 1;
            float sR1[10];
            #pragma unroll
            for (int p3 = 0; p3 < 10; ++p3) {
                float s = 0.f;
                #pragma unroll
                for (int p4 = 0; p4 < 10; ++p4)
                    s += A4[((p3 * 5 + l) * 10 + p4) * 2 + xo] * A5[p4 * 2 + m];
                sR1[p3] = s;
            }
            #pragma unroll
            for (int p2 = 0; p2 < 10; ++p2) {
                float rt = 0.f, sl = 0.f;
                #pragma unroll
                for (int p3 = 0; p3 < 10; ++p3)
                    rt += A3[((p2 * 5 + kk) * 10 + p3) * 5 + w] * sR1[p3];
                #pragma unroll
                for (int p1 = 0; p1 < 10; ++p1)
                    sl += A1[i * 10 + p1] * A2[((p1 * 5 + j) * 10 + p2) * 5 + v];
                val += sl * rt;
            }
        }
        const __nv_bfloat16 hi = __float2bfloat16(val);
        const __nv_bfloat16 lo = __float2bfloat16(val - __bfloat162float(hi));
        g_Bf[e * 8 + hp] = hi;
        g_Bf[e * 8 + 4 + hp] = lo;
    }
    // aux tables: b1/b2 on CTA 1; W2 split across CTAs 2 and 3
    if (blockIdx.x == 1) {
        if (tid < 56) g_b1[tid] = (tid < 50) ? b1[tid] : 0.f;
        if (tid >= 56 && tid < 58) g_b2[tid - 56] = b2[tid - 56];
    }
    if (blockIdx.x == 2 || blockIdx.x == 3) {
        const int t2 = (blockIdx.x - 2) * 56 + tid;
        if (tid < 56) {
            const int v = t2 & 1, r = t2 >> 1;
            float s = 0.f;
            if (r < 50) {
                const int i = r / 25, j = (r / 5) % 5, kq2 = r % 5;
                #pragma unroll
                for (int p1 = 0; p1 < 10; ++p1)
                    #pragma unroll
                    for (int p2 = 0; p2 < 10; ++p2)
                        s += B1[i * 10 + p1] * B2[((p1 * 5 + j) * 10 + p2) * 2 + v] *
                             B3[p2 * 5 + kq2];
            }
            g_W2[t2] = s;
        }
    }
    __syncthreads();
    if (tid == 0)
        asm volatile("red.release.gpu.global.add.u32 [%0], 1;" :: "l"(&g_done) : "memory");

    // ---- grid barrier: wait for all builders ----
    if (tid == 0) {
        unsigned v;
        while (true) {
            asm volatile("ld.acquire.gpu.global.u32 %0, [%1];" : "=r"(v) : "l"(&g_done) : "memory");
            if (v >= gridDim.x) break;
            __nanosleep(64);
        }
    }
    __syncthreads();

    // B prefetch for chunks 0..S-2
    #pragma unroll
    for (int s = 0; s < STAGES - 1; ++s) {
        for (int i = tid; i < 224; i += THREADS)
            cp16(bbase + s * BSTG_F * 4 + i * 16, gB + s * 3584 + i * 16);
        asm volatile("cp.async.commit_group;" ::: "memory");
    }

    float acc[2][7][4];
    #pragma unroll
    for (int rb = 0; rb < 2; ++rb)
        #pragma unroll
        for (int t = 0; t < 7; ++t)
            acc[rb][t][0] = acc[rb][t][1] = acc[rb][t][2] = acc[rb][t][3] = 0.f;

    const float* wsx = sm + warp * XW_F;

    for (int ks = 0; ks < 32; ++ks) {
        const int slot = ks % STAGES;
        asm volatile("cp.async.wait_group %0;" :: "n"(STAGES - 2) : "memory");
        __syncthreads();

        // fetch chunk ks+S-1 into the slot consumed at ks-1 (barrier-fenced)
        const int c = ks + STAGES - 1;
        if (c < 32) {
            const int fslot = c % STAGES;
            load_x_chunk(xwbase + fslot * STAGE_F * 4, xw, c, lane);
            for (int i = tid; i < 224; i += THREADS)
                cp16(bbase + fslot * BSTG_F * 4 + i * 16, gB + c * 3584 + i * 16);
        }
        asm volatile("cp.async.commit_group;" ::: "memory");

        // consume: B fragments to regs, x fragments + split, then MMAs
        const uint4* bst = reinterpret_cast<const uint4*>(sm + O_B_F + slot * BSTG_F);
        uint4 bf[7];
        #pragma unroll
        for (int t = 0; t < 7; ++t)
            bf[t] = bst[t * 32 + lane];

        const float* st = wsx + slot * STAGE_F;
        #pragma unroll
        for (int rb = 0; rb < 2; ++rb) {
            const int rl = rb * 16 + nrow;
            const float2 u00 = *reinterpret_cast<const float2*>(st + rl * ROW_F + 2 * q);
            const float2 u10 = *reinterpret_cast<const float2*>(st + (rl + 8) * ROW_F + 2 * q);
            const float2 u02 = *reinterpret_cast<const float2*>(st + rl * ROW_F + 8 + 2 * q);
            const float2 u12 = *reinterpret_cast<const float2*>(st + (rl + 8) * ROW_F + 8 + 2 * q);
            uint32_t ah0, ah1, ah2, ah3, al0, al1, al2, al3;
            split2(u00.x, u00.y, ah0, al0);
            split2(u10.x, u10.y, ah1, al1);
            split2(u02.x, u02.y, ah2, al2);
            split2(u12.x, u12.y, ah3, al3);
            // term-major: consecutive MMAs hit different accumulators (7-way ILP)
            #pragma unroll
            for (int t = 0; t < 7; ++t)
                mma16816(acc[rb][t], ah0, ah1, ah2, ah3, bf[t].x, bf[t].y);  // hi*hi
            #pragma unroll
            for (int t = 0; t < 7; ++t)
                mma16816(acc[rb][t], ah0, ah1, ah2, ah3, bf[t].z, bf[t].w);  // hi*lo
            #pragma unroll
            for (int t = 0; t < 7; ++t)
                mma16816(acc[rb][t], al0, al1, al2, al3, bf[t].x, bf[t].y);  // lo*hi
        }
    }

    // epilogue: bias + relu + layer2 (56 -> 2), quad reduce, store
    const float b20 = g_b2[0], b21 = g_b2[1];
    const int kq = q * 2;
    #pragma unroll
    for (int rb = 0; rb < 2; ++rb) {
        float s00 = 0.f, s01 = 0.f, s10 = 0.f, s11 = 0.f;
        #pragma unroll
        for (int t = 0; t < 7; ++t) {
            const int n0 = t * 8 + kq;
            const float2 bv = *reinterpret_cast<const float2*>(g_b1 + n0);
            const float4 wv = *reinterpret_cast<const float4*>(g_W2 + 2 * n0);
            float h;
            h = fmaxf(acc[rb][t][0] + bv.x, 0.f); s00 = fmaf(h, wv.x, s00); s01 = fmaf(h, wv.y, s01);
            h = fmaxf(acc[rb][t][1] + bv.y, 0.f); s00 = fmaf(h, wv.z, s00); s01 = fmaf(h, wv.w, s01);
            h = fmaxf(acc[rb][t][2] + bv.x, 0.f); s10 = fmaf(h, wv.x, s10); s11 = fmaf(h, wv.y, s11);
            h = fmaxf(acc[rb][t][3] + bv.y, 0.f); s10 = fmaf(h, wv.z, s10); s11 = fmaf(h, wv.w, s11);
        }
        #pragma unroll
        for (int d = 1; d <= 2; d <<= 1) {
            s00 += __shfl_xor_sync(0xffffffffu, s00, d);
            s01 += __shfl_xor_sync(0xffffffffu, s01, d);
            s10 += __shfl_xor_sync(0xffffffffu, s10, d);
            s11 += __shfl_xor_sync(0xffffffffu, s11, d);
        }
        if (q == 0) {
            const size_t r = row0 + warp * 32 + rb * 16 + nrow;
            *reinterpret_cast<float2*>(out + 2 * r) = make_float2(s00 + b20, s01 + b21);
            *reinterpret_cast<float2*>(out + 2 * (r + 8)) = make_float2(s10 + b20, s11 + b21);
        }
    }

    // reset flags for the next graph replay (last CTA out turns off the lights)
    __syncthreads();
    if (tid == 0) {
        const unsigned prev = atomicAdd(&g_exit, 1u);
        if (prev == gridDim.x - 1) {
            atomicExch(&g_done, 0u);
            atomicExch(&g_exit, 0u);
            __threadfence();
        }
    }
}

extern "C" void kernel_launch(void* const* d_in, const int* in_sizes, int n_in,
                              void* d_out, int out_size) {
    cudaFuncSetAttribute(tn_forward, cudaFuncAttributeMaxDynamicSharedMemorySize, SMEM_TOTAL);
    tn_forward<<<1024, THREADS, SMEM_TOTAL>>>(
        (const float*)d_in[0], (float*)d_out,
        (const float*)d_in[1], (const float*)d_in[2], (const float*)d_in[3],
        (const float*)d_in[4], (const float*)d_in[5], (const float*)d_in[6],
        (const float*)d_in[7], (const float*)d_in[8], (const float*)d_in[9],
        (const float*)d_in[10]);
}

// round 16
// speedup vs baseline: 1.0402x; 1.0402x over previous
#include <cuda_runtime.h>
#include <cuda_bf16.h>
#include <cstdint>

// ---------------------------------------------------------------------------
// g_Bf: W1 bf16 fragments, coalesced uint4 per (ks, t, lane):
//   uint4 index e = (ks*7 + tt)*32 + lane, lane = nr*4 + fq, n = tt*8 + nr
//   bf16[e*8 + half*2+par]   = hi of W1[k = ks*16 + half*8 + fq*2 + par][n]
//   bf16[e*8 + 4+half*2+par] = lo
// Total 7168 uint4 = 114688 B. Each CTA builds uint4s [bid*14, bid*14+14)
// (56 worker threads, one (k,n,half,par) cell each); grid flag gates reads.
// ---------------------------------------------------------------------------
static __device__ __align__(16) __nv_bfloat16 g_Bf[7168 * 8];  // 114688 B
static __device__ __align__(16) float g_W2[112];  // [56][2], rows >= 50 zero
static __device__ __align__(8)  float g_b1[56];   // zero-padded
static __device__ __align__(8)  float g_b2[2];
static __device__ unsigned g_done = 0;  // builder completions (reset at exit)
static __device__ unsigned g_exit = 0;  // CTA exits (reset at exit)

// ---------------- helpers ----------------
__device__ __forceinline__ uint32_t smem_u32(const void* p) {
    uint32_t a;
    asm("{ .reg .u64 t; cvta.to.shared.u64 t, %1; cvt.u32.u64 %0, t; }" : "=r"(a) : "l"(p));
    return a;
}
__device__ __forceinline__ void cp16(uint32_t dst, const void* src) {
    asm volatile("cp.async.cg.shared.global [%0], [%1], 16;" :: "r"(dst), "l"(src) : "memory");
}
__device__ __forceinline__ void cp16z(uint32_t dst, const void* src) {
    asm volatile("cp.async.cg.shared.global [%0], [%1], 16, 0;" :: "r"(dst), "l"(src) : "memory");
}
__device__ __forceinline__ void split2(float vx, float vy, uint32_t& h, uint32_t& l) {
    __nv_bfloat162 hb = __floats2bfloat162_rn(vx, vy);
    float rx = vx - __bfloat162float(hb.x);
    float ry = vy - __bfloat162float(hb.y);
    __nv_bfloat162 lb = __floats2bfloat162_rn(rx, ry);
    h = (uint32_t)__bfloat16_as_ushort(hb.x) | ((uint32_t)__bfloat16_as_ushort(hb.y) << 16);
    l = (uint32_t)__bfloat16_as_ushort(lb.x) | ((uint32_t)__bfloat16_as_ushort(lb.y) << 16);
}
__device__ __forceinline__ void mma16816(float* d, uint32_t a0, uint32_t a1,
                                         uint32_t a2, uint32_t a3,
                                         uint32_t b0, uint32_t b1) {
    asm volatile(
        "mma.sync.aligned.m16n8k16.row.col.f32.bf16.bf16.f32 "
        "{%0,%1,%2,%3}, {%4,%5,%6,%7}, {%8,%9}, {%0,%1,%2,%3};"
        : "+f"(d[0]), "+f"(d[1]), "+f"(d[2]), "+f"(d[3])
        : "r"(a0), "r"(a1), "r"(a2), "r"(a3), "r"(b0), "r"(b1));
}

// ---- smem layout (floats) ----
// x: per-warp 3-stage ring, 32 rows x 20 floats per stage (conflict-free pad).
// B: CTA-shared 3-stage ring, 3584 B per stage.
static constexpr int NW      = 4;                       // warps per CTA
static constexpr int THREADS = NW * 32;                 // 128
static constexpr int ROW_F   = 20;
static constexpr int STAGES  = 3;
static constexpr int STAGE_F = 32 * ROW_F;              // 640 floats
static constexpr int XW_F    = STAGES * STAGE_F;        // 1920 floats / warp
static constexpr int O_B_F   = NW * XW_F;               // 7680
static constexpr int BSTG_F  = 896;                     // 3584 B per B stage
static constexpr int SMEM_TOTAL = (O_B_F + STAGES * BSTG_F) * 4;  // 41472 B

__device__ __forceinline__ void load_x_chunk(uint32_t wstage_b, const float* xw,
                                             int ks, int lane) {
    #pragma unroll
    for (int i = 0; i < 4; ++i) {
        const int c = lane + 32 * i;
        const int rowl = c >> 2, c4 = c & 3;
        const int kb = ks * 16 + c4 * 4;
        const uint32_t dst = wstage_b + (uint32_t)(rowl * ROW_F + c4 * 4) * 4u;
        if (kb + 4 <= 500) cp16(dst, xw + (size_t)rowl * 500 + kb);
        else               cp16z(dst, xw);
    }
}

// ---------------- single fused kernel ----------------
// 512 CTAs x 128 threads, 4 CTAs/SM (single wave). Warp owns 32 rows x 56 cols.
__global__ void __launch_bounds__(THREADS, 4)
tn_forward(const float* __restrict__ x, float* __restrict__ out,
           const float* __restrict__ A1, const float* __restrict__ A2,
           const float* __restrict__ A3, const float* __restrict__ A4,
           const float* __restrict__ A5, const float* __restrict__ b1,
           const float* __restrict__ B1, const float* __restrict__ B2,
           const float* __restrict__ B3, const float* __restrict__ b2) {
    extern __shared__ float sm[];
    const uint32_t sbase = smem_u32(sm);
    const int tid = threadIdx.x;
    const int warp = tid >> 5, lane = tid & 31;
    const int q = lane & 3, nrow = lane >> 2;

    const size_t row0 = (size_t)blockIdx.x * 128;
    const float* xw = x + (row0 + (size_t)warp * 32) * 500;
    const uint32_t xwbase = sbase + (uint32_t)warp * XW_F * 4u;
    const uint32_t bbase = sbase + (uint32_t)O_B_F * 4u;
    const char* gB = reinterpret_cast<const char*>(g_Bf);

    // issue x prefetch for chunks 0..S-2 (uncommitted; overlaps weight build)
    #pragma unroll
    for (int s = 0; s < STAGES - 1; ++s)
        load_x_chunk(xwbase + s * STAGE_F * 4, xw, s, lane);

    // ---- distributed weight build: this CTA owns uint4s [bid*14, bid*14+14) ----
    if (tid < 56) {
        const int u = tid >> 2, hp = tid & 3;
        const int e = blockIdx.x * 14 + u;
        const int lane_f = e & 31, tt = (e >> 5) % 7, ks = (e >> 5) / 7;
        const int nr = lane_f >> 2, fq = lane_f & 3;
        const int n = tt * 8 + nr;
        const int k = ks * 16 + (hp >> 1) * 8 + fq * 2 + (hp & 1);
        float val = 0.f;
        if (k < 500 && n < 50) {
            const int i = k / 250, j = (k / 50) % 5, kk = (k / 10) % 5;
            const int l = (k >> 1) % 5, m = k & 1;
            const int v = n / 10, w = (n >> 1) % 5, xo = n & 1;
            float sR1[10];
            #pragma unroll
            for (int p3 = 0; p3 < 10; ++p3) {
                float s = 0.f;
                #pragma unroll
                for (int p4 = 0; p4 < 10; ++p4)
                    s += A4[((p3 * 5 + l) * 10 + p4) * 2 + xo] * A5[p4 * 2 + m];
                sR1[p3] = s;
            }
            #pragma unroll
            for (int p2 = 0; p2 < 10; ++p2) {
                float rt = 0.f, sl = 0.f;
                #pragma unroll
                for (int p3 = 0; p3 < 10; ++p3)
                    rt += A3[((p2 * 5 + kk) * 10 + p3) * 5 + w] * sR1[p3];
                #pragma unroll
                for (int p1 = 0; p1 < 10; ++p1)
                    sl += A1[i * 10 + p1] * A2[((p1 * 5 + j) * 10 + p2) * 5 + v];
                val += sl * rt;
            }
        }
        const __nv_bfloat16 hi = __float2bfloat16(val);
        const __nv_bfloat16 lo = __float2bfloat16(val - __bfloat162float(hi));
        g_Bf[e * 8 + hp] = hi;
        g_Bf[e * 8 + 4 + hp] = lo;
    }
    // aux tables: W2 on CTA 2, b1/b2 on CTA 1 (all pre-flag)
    if (blockIdx.x == 2 && tid < 112) {
        const int v = tid & 1, r = tid >> 1;
        float s = 0.f;
        if (r < 50) {
            const int i = r / 25, j = (r / 5) % 5, kq2 = r % 5;
            #pragma unroll
            for (int p1 = 0; p1 < 10; ++p1)
                #pragma unroll
                for (int p2 = 0; p2 < 10; ++p2)
                    s += B1[i * 10 + p1] * B2[((p1 * 5 + j) * 10 + p2) * 2 + v] *
                         B3[p2 * 5 + kq2];
        }
        g_W2[tid] = s;
    }
    if (blockIdx.x == 1) {
        if (tid >= 64 && tid < 120) g_b1[tid - 64] = (tid - 64 < 50) ? b1[tid - 64] : 0.f;
        if (tid >= 120 && tid < 122) g_b2[tid - 120] = b2[tid - 120];
    }
    __syncthreads();
    if (tid == 0)
        asm volatile("red.release.gpu.global.add.u32 [%0], 1;" :: "l"(&g_done) : "memory");

    // ---- grid barrier: wait for all 512 builders ----
    if (tid == 0) {
        unsigned v;
        while (true) {
            asm volatile("ld.acquire.gpu.global.u32 %0, [%1];" : "=r"(v) : "l"(&g_done) : "memory");
            if (v >= gridDim.x) break;
            __nanosleep(64);
        }
    }
    __syncthreads();

    // B prefetch for chunks 0..S-2
    #pragma unroll
    for (int s = 0; s < STAGES - 1; ++s) {
        #pragma unroll
        for (int i = tid; i < 224; i += THREADS)
            cp16(bbase + s * BSTG_F * 4 + i * 16, gB + s * 3584 + i * 16);
        asm volatile("cp.async.commit_group;" ::: "memory");
    }

    float acc[2][7][4];
    #pragma unroll
    for (int rb = 0; rb < 2; ++rb)
        #pragma unroll
        for (int t = 0; t < 7; ++t)
            acc[rb][t][0] = acc[rb][t][1] = acc[rb][t][2] = acc[rb][t][3] = 0.f;

    const float* wsx = sm + warp * XW_F;

    for (int ks = 0; ks < 32; ++ks) {
        const int slot = ks % STAGES;
        asm volatile("cp.async.wait_group %0;" :: "n"(STAGES - 2) : "memory");
        __syncthreads();

        // fetch chunk ks+S-1 into the slot consumed at ks-1 (barrier-fenced)
        const int c = ks + STAGES - 1;
        if (c < 32) {
            const int fslot = c % STAGES;
            load_x_chunk(xwbase + fslot * STAGE_F * 4, xw, c, lane);
            #pragma unroll
            for (int i = tid; i < 224; i += THREADS)
                cp16(bbase + fslot * BSTG_F * 4 + i * 16, gB + c * 3584 + i * 16);
        }
        asm volatile("cp.async.commit_group;" ::: "memory");

        // consume: B fragments to regs, x fragments + split, then MMAs
        const uint4* bst = reinterpret_cast<const uint4*>(sm + O_B_F + slot * BSTG_F);
        uint4 bf[7];
        #pragma unroll
        for (int t = 0; t < 7; ++t)
            bf[t] = bst[t * 32 + lane];

        const float* st = wsx + slot * STAGE_F;
        #pragma unroll
        for (int rb = 0; rb < 2; ++rb) {
            const int rl = rb * 16 + nrow;
            const float2 u00 = *reinterpret_cast<const float2*>(st + rl * ROW_F + 2 * q);
            const float2 u10 = *reinterpret_cast<const float2*>(st + (rl + 8) * ROW_F + 2 * q);
            const float2 u02 = *reinterpret_cast<const float2*>(st + rl * ROW_F + 8 + 2 * q);
            const float2 u12 = *reinterpret_cast<const float2*>(st + (rl + 8) * ROW_F + 8 + 2 * q);
            uint32_t ah0, ah1, ah2, ah3, al0, al1, al2, al3;
            split2(u00.x, u00.y, ah0, al0);
            split2(u10.x, u10.y, ah1, al1);
            split2(u02.x, u02.y, ah2, al2);
            split2(u12.x, u12.y, ah3, al3);
            // term-major: consecutive MMAs hit different accumulators (7-way ILP)
            #pragma unroll
            for (int t = 0; t < 7; ++t)
                mma16816(acc[rb][t], ah0, ah1, ah2, ah3, bf[t].x, bf[t].y);  // hi*hi
            #pragma unroll
            for (int t = 0; t < 7; ++t)
                mma16816(acc[rb][t], ah0, ah1, ah2, ah3, bf[t].z, bf[t].w);  // hi*lo
            #pragma unroll
            for (int t = 0; t < 7; ++t)
                mma16816(acc[rb][t], al0, al1, al2, al3, bf[t].x, bf[t].y);  // lo*hi
        }
    }

    // epilogue: bias + relu + layer2 (56 -> 2), quad reduce, store
    const float b20 = g_b2[0], b21 = g_b2[1];
    const int kq = q * 2;
    #pragma unroll
    for (int rb = 0; rb < 2; ++rb) {
        float s00 = 0.f, s01 = 0.f, s10 = 0.f, s11 = 0.f;
        #pragma unroll
        for (int t = 0; t < 7; ++t) {
            const int n0 = t * 8 + kq;
            const float2 bv = *reinterpret_cast<const float2*>(g_b1 + n0);
            const float4 wv = *reinterpret_cast<const float4*>(g_W2 + 2 * n0);
            float h;
            h = fmaxf(acc[rb][t][0] + bv.x, 0.f); s00 = fmaf(h, wv.x, s00); s01 = fmaf(h, wv.y, s01);
            h = fmaxf(acc[rb][t][1] + bv.y, 0.f); s00 = fmaf(h, wv.z, s00); s01 = fmaf(h, wv.w, s01);
            h = fmaxf(acc[rb][t][2] + bv.x, 0.f); s10 = fmaf(h, wv.x, s10); s11 = fmaf(h, wv.y, s11);
            h = fmaxf(acc[rb][t][3] + bv.y, 0.f); s10 = fmaf(h, wv.z, s10); s11 = fmaf(h, wv.w, s11);
        }
        #pragma unroll
        for (int d = 1; d <= 2; d <<= 1) {
            s00 += __shfl_xor_sync(0xffffffffu, s00, d);
            s01 += __shfl_xor_sync(0xffffffffu, s01, d);
            s10 += __shfl_xor_sync(0xffffffffu, s10, d);
            s11 += __shfl_xor_sync(0xffffffffu, s11, d);
        }
        if (q == 0) {
            const size_t r = row0 + warp * 32 + rb * 16 + nrow;
            *reinterpret_cast<float2*>(out + 2 * r) = make_float2(s00 + b20, s01 + b21);
            *reinterpret_cast<float2*>(out + 2 * (r + 8)) = make_float2(s10 + b20, s11 + b21);
        }
    }

    // reset flags for the next graph replay (last CTA out turns off the lights)
    __syncthreads();
    if (tid == 0) {
        const unsigned prev = atomicAdd(&g_exit, 1u);
        if (prev == gridDim.x - 1) {
            atomicExch(&g_done, 0u);
            atomicExch(&g_exit, 0u);
            __threadfence();
        }
    }
}

extern "C" void kernel_launch(void* const* d_in, const int* in_sizes, int n_in,
                              void* d_out, int out_size) {
    cudaFuncSetAttribute(tn_forward, cudaFuncAttributeMaxDynamicSharedMemorySize, SMEM_TOTAL);
    tn_forward<<<512, THREADS, SMEM_TOTAL>>>(
        (const float*)d_in[0], (float*)d_out,
        (const float*)d_in[1], (const float*)d_in[2], (const float*)d_in[3],
        (const float*)d_in[4], (const float*)d_in[5], (const float*)d_in[6],
        (const float*)d_in[7], (const float*)d_in[8], (const float*)d_in[9],
        (const float*)d_in[10]);
}

// round 17
// speedup vs baseline: 1.1237x; 1.0803x over previous
#include <cuda_runtime.h>
#include <cuda_bf16.h>
#include <cstdint>

// ---------------------------------------------------------------------------
// g_Bf: W1 bf16 fragments, coalesced uint4 per (ks, t, lane):
//   uint4 index e = (ks*7 + tt)*32 + lane, lane = nr*4 + fq, n = tt*8 + nr
//   bf16[e*8 + half*2+par]   = hi of W1[k = ks*16 + half*8 + fq*2 + par][n]
//   bf16[e*8 + 4+half*2+par] = lo
// Total 7168 uint4 = 114688 B. Each CTA builds uint4s [bid*14, bid*14+14)
// (56 worker threads, one (k,n,half,par) cell each); grid flag gates reads.
// ---------------------------------------------------------------------------
static __device__ __align__(16) __nv_bfloat16 g_Bf[7168 * 8];  // 114688 B
static __device__ __align__(16) float g_W2[112];  // [56][2], rows >= 50 zero
static __device__ __align__(8)  float g_b1[56];   // zero-padded
static __device__ __align__(8)  float g_b2[2];
static __device__ unsigned g_done = 0;  // builder completions (reset at exit)
static __device__ unsigned g_exit = 0;  // CTA exits (reset at exit)

// ---------------- helpers ----------------
__device__ __forceinline__ uint32_t smem_u32(const void* p) {
    uint32_t a;
    asm("{ .reg .u64 t; cvta.to.shared.u64 t, %1; cvt.u32.u64 %0, t; }" : "=r"(a) : "l"(p));
    return a;
}
__device__ __forceinline__ void cp16(uint32_t dst, const void* src) {
    asm volatile("cp.async.cg.shared.global [%0], [%1], 16;" :: "r"(dst), "l"(src) : "memory");
}
__device__ __forceinline__ void cp16z(uint32_t dst, const void* src) {
    asm volatile("cp.async.cg.shared.global [%0], [%1], 16, 0;" :: "r"(dst), "l"(src) : "memory");
}
// Truncation split: hi = top-16-bits of fp32 (exact), lo = rn_bf16(v - hi).
// v - hi is exact in fp32 (clears high mantissa), so |err| ~ 2^-17 |v|.
__device__ __forceinline__ void split2t(float vx, float vy, uint32_t& h, uint32_t& l) {
    const uint32_t bx = __float_as_uint(vx), by = __float_as_uint(vy);
    h = __byte_perm(bx, by, 0x7632);
    const float hx = __uint_as_float(bx & 0xffff0000u);
    const float hy = __uint_as_float(by & 0xffff0000u);
    __nv_bfloat162 lb = __floats2bfloat162_rn(vx - hx, vy - hy);
    l = *reinterpret_cast<uint32_t*>(&lb);
}
__device__ __forceinline__ void mma16816(float* d, uint32_t a0, uint32_t a1,
                                         uint32_t a2, uint32_t a3,
                                         uint32_t b0, uint32_t b1) {
    asm volatile(
        "mma.sync.aligned.m16n8k16.row.col.f32.bf16.bf16.f32 "
        "{%0,%1,%2,%3}, {%4,%5,%6,%7}, {%8,%9}, {%0,%1,%2,%3};"
        : "+f"(d[0]), "+f"(d[1]), "+f"(d[2]), "+f"(d[3])
        : "r"(a0), "r"(a1), "r"(a2), "r"(a3), "r"(b0), "r"(b1));
}

// ---- smem layout (floats) ----
// Double-size stages: one stage = TWO k16 steps (32 k-floats).
// x: per-warp 2-stage ring, 32 rows x 36 floats (144 B rows: 16B-aligned
//    cp.async dsts; banks 36*nrow+2q cover all even banks once -> conflict-free).
// B: CTA-shared 2-stage ring, 7168 B per stage (two 3584 B k-step blocks).
static constexpr int NW      = 4;                       // warps per CTA
static constexpr int THREADS = NW * 32;                 // 128
static constexpr int ROW_F   = 36;
static constexpr int STAGES  = 2;
static constexpr int STAGE_F = 32 * ROW_F;              // 1152 floats
static constexpr int XW_F    = STAGES * STAGE_F;        // 2304 floats / warp
static constexpr int O_B_F   = NW * XW_F;               // 9216
static constexpr int BSTG_F  = 1792;                    // 7168 B per B stage
static constexpr int SMEM_TOTAL = (O_B_F + STAGES * BSTG_F) * 4;  // 51200 B

// one warp loads 32 rows x 32 floats (4096 B) of x for double-chunk c32
__device__ __forceinline__ void load_x_chunk2(uint32_t wstage_b, const float* xw,
                                              int c32, int lane) {
    #pragma unroll
    for (int i = 0; i < 8; ++i) {
        const int c = lane + 32 * i;
        const int rowl = c >> 3, c8 = c & 7;
        const int kb = c32 * 32 + c8 * 4;
        const uint32_t dst = wstage_b + (uint32_t)(rowl * ROW_F + c8 * 4) * 4u;
        if (kb + 4 <= 500) cp16(dst, xw + (size_t)rowl * 500 + kb);
        else               cp16z(dst, xw);
    }
}

// ---------------- single fused kernel ----------------
// 512 CTAs x 128 threads, 4 CTAs/SM (single wave). Warp owns 32 rows x 56 cols.
__global__ void __launch_bounds__(THREADS, 4)
tn_forward(const float* __restrict__ x, float* __restrict__ out,
           const float* __restrict__ A1, const float* __restrict__ A2,
           const float* __restrict__ A3, const float* __restrict__ A4,
           const float* __restrict__ A5, const float* __restrict__ b1,
           const float* __restrict__ B1, const float* __restrict__ B2,
           const float* __restrict__ B3, const float* __restrict__ b2) {
    extern __shared__ float sm[];
    const uint32_t sbase = smem_u32(sm);
    const int tid = threadIdx.x;
    const int warp = tid >> 5, lane = tid & 31;
    const int q = lane & 3, nrow = lane >> 2;

    const size_t row0 = (size_t)blockIdx.x * 128;
    const float* xw = x + (row0 + (size_t)warp * 32) * 500;
    const uint32_t xwbase = sbase + (uint32_t)warp * XW_F * 4u;
    const uint32_t bbase = sbase + (uint32_t)O_B_F * 4u;
    const char* gB = reinterpret_cast<const char*>(g_Bf);

    // issue x prefetch for double-chunk 0 (uncommitted; overlaps weight build)
    load_x_chunk2(xwbase, xw, 0, lane);

    // ---- distributed weight build: this CTA owns uint4s [bid*14, bid*14+14) ----
    if (tid < 56) {
        const int u = tid >> 2, hp = tid & 3;
        const int e = blockIdx.x * 14 + u;
        const int lane_f = e & 31, tt = (e >> 5) % 7, ks = (e >> 5) / 7;
        const int nr = lane_f >> 2, fq = lane_f & 3;
        const int n = tt * 8 + nr;
        const int k = ks * 16 + (hp >> 1) * 8 + fq * 2 + (hp & 1);
        float val = 0.f;
        if (k < 500 && n < 50) {
            const int i = k / 250, j = (k / 50) % 5, kk = (k / 10) % 5;
            const int l = (k >> 1) % 5, m = k & 1;
            const int v = n / 10, w = (n >> 1) % 5, xo = n & 1;
            float sR1[10];
            #pragma unroll
            for (int p3 = 0; p3 < 10; ++p3) {
                float s = 0.f;
                #pragma unroll
                for (int p4 = 0; p4 < 10; ++p4)
                    s += A4[((p3 * 5 + l) * 10 + p4) * 2 + xo] * A5[p4 * 2 + m];
                sR1[p3] = s;
            }
            #pragma unroll
            for (int p2 = 0; p2 < 10; ++p2) {
                float rt = 0.f, sl = 0.f;
                #pragma unroll
                for (int p3 = 0; p3 < 10; ++p3)
                    rt += A3[((p2 * 5 + kk) * 10 + p3) * 5 + w] * sR1[p3];
                #pragma unroll
                for (int p1 = 0; p1 < 10; ++p1)
                    sl += A1[i * 10 + p1] * A2[((p1 * 5 + j) * 10 + p2) * 5 + v];
                val += sl * rt;
            }
        }
        const __nv_bfloat16 hi = __float2bfloat16(val);
        const __nv_bfloat16 lo = __float2bfloat16(val - __bfloat162float(hi));
        g_Bf[e * 8 + hp] = hi;
        g_Bf[e * 8 + 4 + hp] = lo;
    }
    // aux tables: W2 on CTA 2, b1/b2 on CTA 1 (all pre-flag)
    if (blockIdx.x == 2 && tid < 112) {
        const int v = tid & 1, r = tid >> 1;
        float s = 0.f;
        if (r < 50) {
            const int i = r / 25, j = (r / 5) % 5, kq2 = r % 5;
            #pragma unroll
            for (int p1 = 0; p1 < 10; ++p1)
                #pragma unroll
                for (int p2 = 0; p2 < 10; ++p2)
                    s += B1[i * 10 + p1] * B2[((p1 * 5 + j) * 10 + p2) * 2 + v] *
                         B3[p2 * 5 + kq2];
        }
        g_W2[tid] = s;
    }
    if (blockIdx.x == 1) {
        if (tid >= 64 && tid < 120) g_b1[tid - 64] = (tid - 64 < 50) ? b1[tid - 64] : 0.f;
        if (tid >= 120 && tid < 122) g_b2[tid - 120] = b2[tid - 120];
    }
    __syncthreads();
    if (tid == 0)
        asm volatile("red.release.gpu.global.add.u32 [%0], 1;" :: "l"(&g_done) : "memory");

    // ---- grid barrier: wait for all 512 builders ----
    if (tid == 0) {
        unsigned v;
        while (true) {
            asm volatile("ld.acquire.gpu.global.u32 %0, [%1];" : "=r"(v) : "l"(&g_done) : "memory");
            if (v >= gridDim.x) break;
            __nanosleep(64);
        }
    }
    __syncthreads();

    // B prefetch for double-chunk 0; single commit covers x0+B0
    for (int i = tid; i < 448; i += THREADS)
        cp16(bbase + i * 16, gB + i * 16);
    asm volatile("cp.async.commit_group;" ::: "memory");

    float acc[2][7][4];
    #pragma unroll
    for (int rb = 0; rb < 2; ++rb)
        #pragma unroll
        for (int t = 0; t < 7; ++t)
            acc[rb][t][0] = acc[rb][t][1] = acc[rb][t][2] = acc[rb][t][3] = 0.f;

    const float* wsx = sm + warp * XW_F;

    for (int c32 = 0; c32 < 16; ++c32) {
        const int slot = c32 & 1;
        asm volatile("cp.async.wait_group 0;" ::: "memory");
        __syncthreads();

        // fetch double-chunk c32+1 into the other slot (consumed at c32-1)
        const int nc = c32 + 1;
        if (nc < 16) {
            const int fslot = nc & 1;
            load_x_chunk2(xwbase + fslot * STAGE_F * 4, xw, nc, lane);
            for (int i = tid; i < 448; i += THREADS)
                cp16(bbase + fslot * BSTG_F * 4 + i * 16, gB + nc * 7168 + i * 16);
        }
        asm volatile("cp.async.commit_group;" ::: "memory");

        // consume two k16 substeps
        const float* st = wsx + slot * STAGE_F;
        const uint4* bstage = reinterpret_cast<const uint4*>(sm + O_B_F + slot * BSTG_F);
        #pragma unroll
        for (int s2 = 0; s2 < 2; ++s2) {
            const uint4* bst = bstage + s2 * 224;
            uint4 bf[7];
            #pragma unroll
            for (int t = 0; t < 7; ++t)
                bf[t] = bst[t * 32 + lane];

            const int ko = s2 * 16;
            #pragma unroll
            for (int rb = 0; rb < 2; ++rb) {
                const int rl = rb * 16 + nrow;
                const float2 u00 = *reinterpret_cast<const float2*>(st + rl * ROW_F + ko + 2 * q);
                const float2 u10 = *reinterpret_cast<const float2*>(st + (rl + 8) * ROW_F + ko + 2 * q);
                const float2 u02 = *reinterpret_cast<const float2*>(st + rl * ROW_F + ko + 8 + 2 * q);
                const float2 u12 = *reinterpret_cast<const float2*>(st + (rl + 8) * ROW_F + ko + 8 + 2 * q);
                uint32_t ah0, ah1, ah2, ah3, al0, al1, al2, al3;
                split2t(u00.x, u00.y, ah0, al0);
                split2t(u10.x, u10.y, ah1, al1);
                split2t(u02.x, u02.y, ah2, al2);
                split2t(u12.x, u12.y, ah3, al3);
                #pragma unroll
                for (int t = 0; t < 7; ++t)
                    mma16816(acc[rb][t], ah0, ah1, ah2, ah3, bf[t].x, bf[t].y);  // hi*hi
                #pragma unroll
                for (int t = 0; t < 7; ++t)
                    mma16816(acc[rb][t], ah0, ah1, ah2, ah3, bf[t].z, bf[t].w);  // hi*lo
                #pragma unroll
                for (int t = 0; t < 7; ++t)
                    mma16816(acc[rb][t], al0, al1, al2, al3, bf[t].x, bf[t].y);  // lo*hi
            }
        }
    }

    // epilogue: bias + relu + layer2 (56 -> 2), quad reduce, store
    const float b20 = g_b2[0], b21 = g_b2[1];
    const int kq = q * 2;
    #pragma unroll
    for (int rb = 0; rb < 2; ++rb) {
        float s00 = 0.f, s01 = 0.f, s10 = 0.f, s11 = 0.f;
        #pragma unroll
        for (int t = 0; t < 7; ++t) {
            const int n0 = t * 8 + kq;
            const float2 bv = *reinterpret_cast<const float2*>(g_b1 + n0);
            const float4 wv = *reinterpret_cast<const float4*>(g_W2 + 2 * n0);
            float h;
            h = fmaxf(acc[rb][t][0] + bv.x, 0.f); s00 = fmaf(h, wv.x, s00); s01 = fmaf(h, wv.y, s01);
            h = fmaxf(acc[rb][t][1] + bv.y, 0.f); s00 = fmaf(h, wv.z, s00); s01 = fmaf(h, wv.w, s01);
            h = fmaxf(acc[rb][t][2] + bv.x, 0.f); s10 = fmaf(h, wv.x, s10); s11 = fmaf(h, wv.y, s11);
            h = fmaxf(acc[rb][t][3] + bv.y, 0.f); s10 = fmaf(h, wv.z, s10); s11 = fmaf(h, wv.w, s11);
        }
        #pragma unroll
        for (int d = 1; d <= 2; d <<= 1) {
            s00 += __shfl_xor_sync(0xffffffffu, s00, d);
            s01 += __shfl_xor_sync(0xffffffffu, s01, d);
            s10 += __shfl_xor_sync(0xffffffffu, s10, d);
            s11 += __shfl_xor_sync(0xffffffffu, s11, d);
        }
        if (q == 0) {
            const size_t r = row0 + warp * 32 + rb * 16 + nrow;
            *reinterpret_cast<float2*>(out + 2 * r) = make_float2(s00 + b20, s01 + b21);
            *reinterpret_cast<float2*>(out + 2 * (r + 8)) = make_float2(s10 + b20, s11 + b21);
        }
    }

    // reset flags for the next graph replay (last CTA out turns off the lights)
    __syncthreads();
    if (tid == 0) {
        const unsigned prev = atomicAdd(&g_exit, 1u);
        if (prev == gridDim.x - 1) {
            atomicExch(&g_done, 0u);
            atomicExch(&g_exit, 0u);
            __threadfence();
        }
    }
}

extern "C" void kernel_launch(void* const* d_in, const int* in_sizes, int n_in,
                              void* d_out, int out_size) {
    cudaFuncSetAttribute(tn_forward, cudaFuncAttributeMaxDynamicSharedMemorySize, SMEM_TOTAL);
    tn_forward<<<512, THREADS, SMEM_TOTAL>>>(
        (const float*)d_in[0], (float*)d_out,
        (const float*)d_in[1], (const float*)d_in[2], (const float*)d_in[3],
        (const float*)d_in[4], (const float*)d_in[5], (const float*)d_in[6],
        (const float*)d_in[7], (const float*)d_in[8], (const float*)d_in[9],
        (const float*)d_in[10]);
}